// round 15
// baseline (speedup 1.0000x reference)
#include <cuda_runtime.h>

#define N_NODES 100000
#define N_EDGES 1600000
#define SEG 64   // fixed CSR segment per node (max degree ~45 for Poisson(16))

// Scratch (no cudaMalloc allowed). Ping-pong buffers A and B.
__device__ float A_buf[N_NODES * 32];
__device__ float B_buf[N_NODES * 32];
__device__ float dinv_buf[N_NODES];        // rsqrt(deg+1)
__device__ int   cursor_buf[N_NODES];      // fill cursors; zero at entry (static init, reset by agg2)
__device__ int   csr_src[N_NODES * SEG];   // src grouped by dst, fixed stride

// ---------------- fill: 4 edges/thread; per-block dtype detect ----------------
// int64 little-endian with ids < 2^31: all odd int32 words zero.
__global__ void fill_kernel(const int* __restrict__ ei) {
    __shared__ int is64_sh;
    if (threadIdx.x == 0) {
        int any = 0;
        for (int k = 0; k < 64; k++) any |= ei[2 * k + 1];
        is64_sh = (any == 0) ? 1 : 0;
    }
    __syncthreads();
    int t = blockIdx.x * blockDim.x + threadIdx.x;
    if (t >= N_EDGES / 4) return;
    int4 s, d;
    if (is64_sh) {
        const int4* p = reinterpret_cast<const int4*>(ei);
        int4 s0 = p[2 * t], s1 = p[2 * t + 1];
        int4 d0 = p[N_EDGES / 2 + 2 * t], d1 = p[N_EDGES / 2 + 2 * t + 1];
        s = make_int4(s0.x, s0.z, s1.x, s1.z);
        d = make_int4(d0.x, d0.z, d1.x, d1.z);
    } else {
        s = reinterpret_cast<const int4*>(ei)[t];
        d = reinterpret_cast<const int4*>(ei + N_EDGES)[t];
    }
    int p0 = atomicAdd(&cursor_buf[d.x], 1);
    int p1 = atomicAdd(&cursor_buf[d.y], 1);
    int p2 = atomicAdd(&cursor_buf[d.z], 1);
    int p3 = atomicAdd(&cursor_buf[d.w], 1);
    if (p0 < SEG) csr_src[d.x * SEG + p0] = s.x;
    if (p1 < SEG) csr_src[d.y * SEG + p1] = s.y;
    if (p2 < SEG) csr_src[d.z * SEG + p2] = s.z;
    if (p3 < SEG) csr_src[d.w * SEG + p3] = s.w;
}

// ---------------- pad: dinv from degree + scaled/padded x ----------------
__global__ void pad_kernel(const float* __restrict__ x) {
    int i = blockIdx.x * blockDim.x + threadIdx.x;
    if (i >= N_NODES) return;
    int deg = cursor_buf[i]; if (deg > SEG) deg = SEG;
    float d = rsqrtf((float)(deg + 1));
    dinv_buf[i] = d;
    float r[20];
#pragma unroll
    for (int c = 0; c < 18; c++) r[c] = d * x[i * 18 + c];
    r[18] = 0.0f; r[19] = 0.0f;
    float4* a4 = reinterpret_cast<float4*>(&A_buf[i * 32]);
#pragma unroll
    for (int q = 0; q < 5; q++)
        a4[q] = make_float4(r[q * 4], r[q * 4 + 1], r[q * 4 + 2], r[q * 4 + 3]);
}

__device__ __forceinline__ int node_deg(int i) {
    int deg = cursor_buf[i];
    return (deg > SEG) ? SEG : deg;
}

// ---------------- layer 1 aggregation: 8-lane group per node, 4 nodes/warp ----------------
// Only quads 0-4 are meaningful; lanes q>=5 idle on data.
__global__ void agg_pre_kernel() {
    int gtid = blockIdx.x * blockDim.x + threadIdx.x;
    int node = gtid >> 3;
    if (node >= N_NODES) return;
    int q = threadIdx.x & 7;
    const float4* A4 = reinterpret_cast<const float4*>(A_buf);
    int deg = node_deg(node);
    int beg = node * SEG;
    bool act = (q < 5);
    float4 acc = act ? A4[node * 8 + q] : make_float4(0.f, 0.f, 0.f, 0.f);  // self loop
#pragma unroll 8
    for (int k = 0; k < deg; k++) {
        int s = csr_src[beg + k];
        if (act) {
            float4 v = A4[s * 8 + q];
            acc.x += v.x; acc.y += v.y; acc.z += v.z; acc.w += v.w;
        }
    }
    if (act) {
        float d = dinv_buf[node];
        reinterpret_cast<float4*>(B_buf)[node * 8 + q] =
            make_float4(d * acc.x, d * acc.y, d * acc.z, d * acc.w);
    }
}

// ---------------- fused GEMM1(+relu)+GEMM2: split-K, 2 threads per node ----------------
// Thread t of node i handles h channels k in [32t, 32t+32); partial o[32] reduced via shfl_xor(1).
__global__ void gemm12_kernel(const float* __restrict__ W1, const float* __restrict__ b1,
                              const float* __restrict__ W2) {
    __shared__ float W1t[64 * 20];
    __shared__ float W2s[64 * 32];
    __shared__ float b1s[64];
    for (int t = threadIdx.x; t < 18 * 64; t += blockDim.x) {
        int m = t / 64, k = t % 64;
        W1t[k * 20 + m] = W1[t];
    }
    for (int t = threadIdx.x; t < 64 * 32; t += blockDim.x) W2s[t] = W2[t];
    for (int t = threadIdx.x; t < 64; t += blockDim.x) b1s[t] = b1[t];
    __syncthreads();

    int gtid = blockIdx.x * blockDim.x + threadIdx.x;
    int i = gtid >> 1;
    if (i >= N_NODES) return;
    int half = gtid & 1;
    int k0 = half * 32;

    float xr[18];
    const float4* x4 = reinterpret_cast<const float4*>(&B_buf[i * 32]);
#pragma unroll
    for (int q = 0; q < 4; q++) {
        float4 v = x4[q];
        xr[q * 4 + 0] = v.x; xr[q * 4 + 1] = v.y; xr[q * 4 + 2] = v.z; xr[q * 4 + 3] = v.w;
    }
    { float2 v = reinterpret_cast<const float2*>(&B_buf[i * 32])[8]; xr[16] = v.x; xr[17] = v.y; }

    float o[32];
#pragma unroll
    for (int j = 0; j < 32; j++) o[j] = 0.0f;

#pragma unroll 2
    for (int kk = 0; kk < 32; kk++) {
        int k = k0 + kk;
        const float4* w1 = reinterpret_cast<const float4*>(&W1t[k * 20]);
        float acc = b1s[k];
#pragma unroll
        for (int q = 0; q < 4; q++) {
            float4 w = w1[q];
            acc += xr[q * 4 + 0] * w.x + xr[q * 4 + 1] * w.y
                 + xr[q * 4 + 2] * w.z + xr[q * 4 + 3] * w.w;
        }
        acc += xr[16] * W1t[k * 20 + 16] + xr[17] * W1t[k * 20 + 17];
        float h = fmaxf(acc, 0.0f);
        const float4* w2 = reinterpret_cast<const float4*>(&W2s[k * 32]);
#pragma unroll
        for (int q = 0; q < 8; q++) {
            float4 w = w2[q];
            o[q * 4 + 0] += h * w.x; o[q * 4 + 1] += h * w.y;
            o[q * 4 + 2] += h * w.z; o[q * 4 + 3] += h * w.w;
        }
    }
    // combine the two K-halves (pair lanes differ only in bit 0)
#pragma unroll
    for (int j = 0; j < 32; j++) o[j] += __shfl_xor_sync(0xffffffffu, o[j], 1);

    // each thread of the pair writes half the row (quads [half*4, half*4+4))
    float d = dinv_buf[i];
    float4* a4 = reinterpret_cast<float4*>(&A_buf[i * 32]);
#pragma unroll
    for (int q = 0; q < 4; q++) {
        int j = half * 16 + q * 4;
        a4[half * 4 + q] = make_float4(d * o[j], d * o[j + 1], d * o[j + 2], d * o[j + 3]);
    }
}

// ---------------- layer 2 agg + fused GEMM3: A(g32) -> B(g16) ----------------
// 8-lane group per node, 4 nodes/warp; epilogue via width-8 shuffles.
__global__ void agg32_g3_kernel(const float* __restrict__ b2, const float* __restrict__ W3) {
    __shared__ float W3s[32 * 16];
    for (int t = threadIdx.x; t < 32 * 16; t += blockDim.x) W3s[t] = W3[t];
    __syncthreads();

    int gtid = blockIdx.x * blockDim.x + threadIdx.x;
    int node = gtid >> 3;
    if (node >= N_NODES) return;
    int q = threadIdx.x & 7;
    const float4* A4 = reinterpret_cast<const float4*>(A_buf);

    int deg = node_deg(node);
    int beg = node * SEG;
    float4 acc = A4[node * 8 + q];  // self loop
#pragma unroll 8
    for (int k = 0; k < deg; k++) {
        int s = csr_src[beg + k];
        float4 v = A4[s * 8 + q];
        acc.x += v.x; acc.y += v.y; acc.z += v.z; acc.w += v.w;
    }

    float d = dinv_buf[node];
    float4 bq = reinterpret_cast<const float4*>(b2)[q];
    float4 h;
    h.x = fmaxf(fmaf(d, acc.x, bq.x), 0.0f);
    h.y = fmaxf(fmaf(d, acc.y, bq.y), 0.0f);
    h.z = fmaxf(fmaf(d, acc.z, bq.z), 0.0f);
    h.w = fmaxf(fmaf(d, acc.w, bq.w), 0.0f);

    int j0 = q * 2;
    float o0 = 0.0f, o1 = 0.0f;
#pragma unroll
    for (int src = 0; src < 8; src++) {
        float hx = __shfl_sync(0xffffffffu, h.x, src, 8);
        float hy = __shfl_sync(0xffffffffu, h.y, src, 8);
        float hz = __shfl_sync(0xffffffffu, h.z, src, 8);
        float hw = __shfl_sync(0xffffffffu, h.w, src, 8);
        const float* w0 = &W3s[(src * 4) * 16 + j0];
        o0 += hx * w0[0]  + hy * w0[16] + hz * w0[32] + hw * w0[48];
        o1 += hx * w0[1]  + hy * w0[17] + hz * w0[33] + hw * w0[49];
    }
    reinterpret_cast<float2*>(B_buf)[node * 8 + q] = make_float2(d * o0, d * o1);
}

// ---------------- layer 3 agg + fused GEMM4: B(g16) -> A(g2) ----------------
// 4-lane group per node, 8 nodes/warp.
__global__ void agg16_g4_kernel(const float* __restrict__ b3, const float* __restrict__ W4) {
    int gtid = blockIdx.x * blockDim.x + threadIdx.x;
    int node = gtid >> 2;
    if (node >= N_NODES) return;
    int q = threadIdx.x & 3;
    const float4* B4 = reinterpret_cast<const float4*>(B_buf);

    int beg = node * SEG;
    int deg = node_deg(node);
    float4 acc = B4[node * 4 + q];  // self loop
#pragma unroll 8
    for (int k = 0; k < deg; k++) {
        int s = csr_src[beg + k];
        float4 v = B4[s * 4 + q];
        acc.x += v.x; acc.y += v.y; acc.z += v.z; acc.w += v.w;
    }

    float d = dinv_buf[node];
    float4 bq = reinterpret_cast<const float4*>(b3)[q];
    float4 h;
    h.x = fmaxf(fmaf(d, acc.x, bq.x), 0.0f);
    h.y = fmaxf(fmaf(d, acc.y, bq.y), 0.0f);
    h.z = fmaxf(fmaf(d, acc.z, bq.z), 0.0f);
    h.w = fmaxf(fmaf(d, acc.w, bq.w), 0.0f);

    int c0 = q * 4;
    float v0 = h.x * W4[(c0 + 0) * 2 + 0] + h.y * W4[(c0 + 1) * 2 + 0]
             + h.z * W4[(c0 + 2) * 2 + 0] + h.w * W4[(c0 + 3) * 2 + 0];
    float v1 = h.x * W4[(c0 + 0) * 2 + 1] + h.y * W4[(c0 + 1) * 2 + 1]
             + h.z * W4[(c0 + 2) * 2 + 1] + h.w * W4[(c0 + 3) * 2 + 1];
#pragma unroll
    for (int o = 1; o <= 2; o <<= 1) {
        v0 += __shfl_xor_sync(0xffffffffu, v0, o);
        v1 += __shfl_xor_sync(0xffffffffu, v1, o);
    }
    if (q == 0) {
        A_buf[node * 2 + 0] = d * v0;
        A_buf[node * 2 + 1] = d * v1;
    }
}

// ---------------- final: agg + bias + log_softmax + cursor reset ----------------
__global__ void agg2_logsoftmax_kernel(const float* __restrict__ b, float* __restrict__ out) {
    int i = blockIdx.x * blockDim.x + threadIdx.x;
    if (i >= N_NODES) return;
    const float2* g2 = reinterpret_cast<const float2*>(A_buf);
    float2 a = g2[i];
    int beg = i * SEG, end = beg + node_deg(i);
#pragma unroll 8
    for (int k = beg; k < end; k++) {
        float2 v = g2[csr_src[k]];
        a.x += v.x; a.y += v.y;
    }
    float d = dinv_buf[i];
    float v0 = fmaf(d, a.x, b[0]);
    float v1 = fmaf(d, a.y, b[1]);
    float m = fmaxf(v0, v1);
    float lse = m + logf(expf(v0 - m) + expf(v1 - m));
    out[i * 2 + 0] = v0 - lse;
    out[i * 2 + 1] = v1 - lse;

    cursor_buf[i] = 0;  // restore invariant for next call
}

// ---------------- launch ----------------

extern "C" void kernel_launch(void* const* d_in, const int* in_sizes, int n_in,
                              void* d_out, int out_size) {
    const float* x  = (const float*)d_in[0];
    const int*   ei = (const int*)d_in[1];
    const float* W1 = (const float*)d_in[2];
    const float* b1 = (const float*)d_in[3];
    const float* W2 = (const float*)d_in[4];
    const float* b2 = (const float*)d_in[5];
    const float* W3 = (const float*)d_in[6];
    const float* b3 = (const float*)d_in[7];
    const float* W4 = (const float*)d_in[8];
    const float* b4 = (const float*)d_in[9];
    float* out = (float*)d_out;

    const int T = 256;
    const int nodeB = (N_NODES + T - 1) / T;
    const int quadEdgeB = (N_EDGES / 4 + T - 1) / T;

    // CSR build (fixed-stride segments; cursors pre-zeroed invariant)
    fill_kernel<<<quadEdgeB, T>>>(ei);
    pad_kernel<<<nodeB, T>>>(x);

    // Layer 1 agg (8-lane groups, 5 active), then fused GEMM1+relu+GEMM2 (2 threads/node)
    agg_pre_kernel<<<(N_NODES * 8 + T - 1) / T, T>>>();
    gemm12_kernel<<<(N_NODES * 2 + T - 1) / T, T>>>(W1, b1, W2);

    // Layer 2 agg + fused GEMM3 (8-lane groups)
    agg32_g3_kernel<<<(N_NODES * 8 + T - 1) / T, T>>>(b2, W3);

    // Layer 3 agg + fused GEMM4 (4-lane groups)
    agg16_g4_kernel<<<(N_NODES * 4 + T - 1) / T, T>>>(b3, W4);

    // Layer 4 agg + log_softmax (+ cursor reset)
    agg2_logsoftmax_kernel<<<nodeB, T>>>(b4, out);
}

// round 16
// speedup vs baseline: 1.1688x; 1.1688x over previous
#include <cuda_runtime.h>

#define N_NODES 100000
#define N_EDGES 1600000
#define SEG 64   // fixed CSR segment per node (max degree ~45 for Poisson(16))

// Scratch (no cudaMalloc allowed). Ping-pong buffers A and B.
__device__ float A_buf[N_NODES * 32];
__device__ float B_buf[N_NODES * 32];
__device__ float dinv_buf[N_NODES];        // rsqrt(deg+1)
__device__ int   cursor_buf[N_NODES];      // fill cursors; zero at entry (static init, reset by agg2)
__device__ int   csr_src[N_NODES * SEG];   // src grouped by dst, fixed stride

// ---------------- fill: 4 edges/thread; per-block dtype detect ----------------
// int64 little-endian with ids < 2^31: all odd int32 words zero.
__global__ void fill_kernel(const int* __restrict__ ei) {
    __shared__ int is64_sh;
    if (threadIdx.x == 0) {
        int any = 0;
        for (int k = 0; k < 64; k++) any |= ei[2 * k + 1];
        is64_sh = (any == 0) ? 1 : 0;
    }
    __syncthreads();
    int t = blockIdx.x * blockDim.x + threadIdx.x;
    if (t >= N_EDGES / 4) return;
    int4 s, d;
    if (is64_sh) {
        const int4* p = reinterpret_cast<const int4*>(ei);
        int4 s0 = p[2 * t], s1 = p[2 * t + 1];
        int4 d0 = p[N_EDGES / 2 + 2 * t], d1 = p[N_EDGES / 2 + 2 * t + 1];
        s = make_int4(s0.x, s0.z, s1.x, s1.z);
        d = make_int4(d0.x, d0.z, d1.x, d1.z);
    } else {
        s = reinterpret_cast<const int4*>(ei)[t];
        d = reinterpret_cast<const int4*>(ei + N_EDGES)[t];
    }
    int p0 = atomicAdd(&cursor_buf[d.x], 1);
    int p1 = atomicAdd(&cursor_buf[d.y], 1);
    int p2 = atomicAdd(&cursor_buf[d.z], 1);
    int p3 = atomicAdd(&cursor_buf[d.w], 1);
    if (p0 < SEG) csr_src[d.x * SEG + p0] = s.x;
    if (p1 < SEG) csr_src[d.y * SEG + p1] = s.y;
    if (p2 < SEG) csr_src[d.z * SEG + p2] = s.z;
    if (p3 < SEG) csr_src[d.w * SEG + p3] = s.w;
}

// ---------------- pad: dinv from degree + scaled/padded x ----------------
__global__ void pad_kernel(const float* __restrict__ x) {
    int i = blockIdx.x * blockDim.x + threadIdx.x;
    if (i >= N_NODES) return;
    int deg = cursor_buf[i]; if (deg > SEG) deg = SEG;
    float d = rsqrtf((float)(deg + 1));
    dinv_buf[i] = d;
    float r[20];
#pragma unroll
    for (int c = 0; c < 18; c++) r[c] = d * x[i * 18 + c];
    r[18] = 0.0f; r[19] = 0.0f;
    float4* a4 = reinterpret_cast<float4*>(&A_buf[i * 32]);
#pragma unroll
    for (int q = 0; q < 5; q++)
        a4[q] = make_float4(r[q * 4], r[q * 4 + 1], r[q * 4 + 2], r[q * 4 + 3]);
}

__device__ __forceinline__ int node_deg(int i) {
    int deg = cursor_buf[i];
    return (deg > SEG) ? SEG : deg;
}

// ---------------- layer 1 aggregation: 8-lane group per node, 4 nodes/warp ----------------
// Only quads 0-4 are meaningful; lanes q>=5 idle on data.
__global__ void agg_pre_kernel() {
    int gtid = blockIdx.x * blockDim.x + threadIdx.x;
    int node = gtid >> 3;
    if (node >= N_NODES) return;
    int q = threadIdx.x & 7;
    const float4* A4 = reinterpret_cast<const float4*>(A_buf);
    int deg = node_deg(node);
    int beg = node * SEG;
    bool act = (q < 5);
    float4 acc = act ? A4[node * 8 + q] : make_float4(0.f, 0.f, 0.f, 0.f);  // self loop
#pragma unroll 8
    for (int k = 0; k < deg; k++) {
        int s = csr_src[beg + k];
        if (act) {
            float4 v = A4[s * 8 + q];
            acc.x += v.x; acc.y += v.y; acc.z += v.z; acc.w += v.w;
        }
    }
    if (act) {
        float d = dinv_buf[node];
        reinterpret_cast<float4*>(B_buf)[node * 8 + q] =
            make_float4(d * acc.x, d * acc.y, d * acc.z, d * acc.w);
    }
}

// ---------------- fused GEMM1(+relu)+GEMM2: B(aggx, 18 valid of 32) -> A(g32) ----------------
// Bias folded into W1t row 18 (xr[18] = 1); row 19 = 0. All smem addresses warp-uniform.
__global__ void gemm12_kernel(const float* __restrict__ W1, const float* __restrict__ b1,
                              const float* __restrict__ W2) {
    __shared__ float W1t[64 * 20];
    __shared__ float W2s[64 * 32];
    for (int t = threadIdx.x; t < 18 * 64; t += blockDim.x) {
        int m = t / 64, k = t % 64;
        W1t[k * 20 + m] = W1[t];
    }
    for (int t = threadIdx.x; t < 64; t += blockDim.x) {
        W1t[t * 20 + 18] = b1[t];
        W1t[t * 20 + 19] = 0.0f;
    }
    for (int t = threadIdx.x; t < 64 * 32; t += blockDim.x) W2s[t] = W2[t];
    __syncthreads();

    int i = blockIdx.x * blockDim.x + threadIdx.x;
    if (i >= N_NODES) return;

    float xr[20];
    const float4* x4 = reinterpret_cast<const float4*>(&B_buf[i * 32]);
#pragma unroll
    for (int q = 0; q < 4; q++) {
        float4 v = x4[q];
        xr[q * 4 + 0] = v.x; xr[q * 4 + 1] = v.y; xr[q * 4 + 2] = v.z; xr[q * 4 + 3] = v.w;
    }
    { float2 v = reinterpret_cast<const float2*>(&B_buf[i * 32])[8]; xr[16] = v.x; xr[17] = v.y; }
    xr[18] = 1.0f;  // bias slot
    xr[19] = 0.0f;

    float o[32];
#pragma unroll
    for (int j = 0; j < 32; j++) o[j] = 0.0f;

#pragma unroll 2
    for (int k = 0; k < 64; k++) {
        const float4* w1 = reinterpret_cast<const float4*>(&W1t[k * 20]);
        float acc = 0.0f;
#pragma unroll
        for (int q = 0; q < 5; q++) {
            float4 w = w1[q];
            acc += xr[q * 4 + 0] * w.x + xr[q * 4 + 1] * w.y
                 + xr[q * 4 + 2] * w.z + xr[q * 4 + 3] * w.w;
        }
        float h = fmaxf(acc, 0.0f);
        const float4* w2 = reinterpret_cast<const float4*>(&W2s[k * 32]);
#pragma unroll
        for (int q = 0; q < 8; q++) {
            float4 w = w2[q];
            o[q * 4 + 0] += h * w.x; o[q * 4 + 1] += h * w.y;
            o[q * 4 + 2] += h * w.z; o[q * 4 + 3] += h * w.w;
        }
    }
    float d = dinv_buf[i];
    float4* a4 = reinterpret_cast<float4*>(&A_buf[i * 32]);
#pragma unroll
    for (int q = 0; q < 8; q++)
        a4[q] = make_float4(d * o[q * 4], d * o[q * 4 + 1], d * o[q * 4 + 2], d * o[q * 4 + 3]);
}

// ---------------- layer 2 agg + fused GEMM3: A(g32) -> B(g16) ----------------
// 8-lane group per node, 4 nodes/warp; epilogue via width-8 shuffles.
__global__ void agg32_g3_kernel(const float* __restrict__ b2, const float* __restrict__ W3) {
    __shared__ float W3s[32 * 16];
    for (int t = threadIdx.x; t < 32 * 16; t += blockDim.x) W3s[t] = W3[t];
    __syncthreads();

    int gtid = blockIdx.x * blockDim.x + threadIdx.x;
    int node = gtid >> 3;
    if (node >= N_NODES) return;
    int q = threadIdx.x & 7;
    const float4* A4 = reinterpret_cast<const float4*>(A_buf);

    int deg = node_deg(node);
    int beg = node * SEG;
    float4 acc = A4[node * 8 + q];  // self loop
#pragma unroll 8
    for (int k = 0; k < deg; k++) {
        int s = csr_src[beg + k];
        float4 v = A4[s * 8 + q];
        acc.x += v.x; acc.y += v.y; acc.z += v.z; acc.w += v.w;
    }

    float d = dinv_buf[node];
    float4 bq = reinterpret_cast<const float4*>(b2)[q];
    float4 h;
    h.x = fmaxf(fmaf(d, acc.x, bq.x), 0.0f);
    h.y = fmaxf(fmaf(d, acc.y, bq.y), 0.0f);
    h.z = fmaxf(fmaf(d, acc.z, bq.z), 0.0f);
    h.w = fmaxf(fmaf(d, acc.w, bq.w), 0.0f);

    int j0 = q * 2;
    float o0 = 0.0f, o1 = 0.0f;
#pragma unroll
    for (int src = 0; src < 8; src++) {
        float hx = __shfl_sync(0xffffffffu, h.x, src, 8);
        float hy = __shfl_sync(0xffffffffu, h.y, src, 8);
        float hz = __shfl_sync(0xffffffffu, h.z, src, 8);
        float hw = __shfl_sync(0xffffffffu, h.w, src, 8);
        const float* w0 = &W3s[(src * 4) * 16 + j0];
        o0 += hx * w0[0]  + hy * w0[16] + hz * w0[32] + hw * w0[48];
        o1 += hx * w0[1]  + hy * w0[17] + hz * w0[33] + hw * w0[49];
    }
    reinterpret_cast<float2*>(B_buf)[node * 8 + q] = make_float2(d * o0, d * o1);
}

// ---------------- layer 3 agg + fused GEMM4: B(g16) -> A(g2) ----------------
// 4-lane group per node, 8 nodes/warp.
__global__ void agg16_g4_kernel(const float* __restrict__ b3, const float* __restrict__ W4) {
    int gtid = blockIdx.x * blockDim.x + threadIdx.x;
    int node = gtid >> 2;
    if (node >= N_NODES) return;
    int q = threadIdx.x & 3;
    const float4* B4 = reinterpret_cast<const float4*>(B_buf);

    int beg = node * SEG;
    int deg = node_deg(node);
    float4 acc = B4[node * 4 + q];  // self loop
#pragma unroll 8
    for (int k = 0; k < deg; k++) {
        int s = csr_src[beg + k];
        float4 v = B4[s * 4 + q];
        acc.x += v.x; acc.y += v.y; acc.z += v.z; acc.w += v.w;
    }

    float d = dinv_buf[node];
    float4 bq = reinterpret_cast<const float4*>(b3)[q];
    float4 h;
    h.x = fmaxf(fmaf(d, acc.x, bq.x), 0.0f);
    h.y = fmaxf(fmaf(d, acc.y, bq.y), 0.0f);
    h.z = fmaxf(fmaf(d, acc.z, bq.z), 0.0f);
    h.w = fmaxf(fmaf(d, acc.w, bq.w), 0.0f);

    int c0 = q * 4;
    float v0 = h.x * W4[(c0 + 0) * 2 + 0] + h.y * W4[(c0 + 1) * 2 + 0]
             + h.z * W4[(c0 + 2) * 2 + 0] + h.w * W4[(c0 + 3) * 2 + 0];
    float v1 = h.x * W4[(c0 + 0) * 2 + 1] + h.y * W4[(c0 + 1) * 2 + 1]
             + h.z * W4[(c0 + 2) * 2 + 1] + h.w * W4[(c0 + 3) * 2 + 1];
#pragma unroll
    for (int o = 1; o <= 2; o <<= 1) {
        v0 += __shfl_xor_sync(0xffffffffu, v0, o);
        v1 += __shfl_xor_sync(0xffffffffu, v1, o);
    }
    if (q == 0) {
        A_buf[node * 2 + 0] = d * v0;
        A_buf[node * 2 + 1] = d * v1;
    }
}

// ---------------- final: agg + bias + log_softmax + cursor reset ----------------
__global__ void agg2_logsoftmax_kernel(const float* __restrict__ b, float* __restrict__ out) {
    int i = blockIdx.x * blockDim.x + threadIdx.x;
    if (i >= N_NODES) return;
    const float2* g2 = reinterpret_cast<const float2*>(A_buf);
    float2 a = g2[i];
    int beg = i * SEG, end = beg + node_deg(i);
#pragma unroll 8
    for (int k = beg; k < end; k++) {
        float2 v = g2[csr_src[k]];
        a.x += v.x; a.y += v.y;
    }
    float d = dinv_buf[i];
    float v0 = fmaf(d, a.x, b[0]);
    float v1 = fmaf(d, a.y, b[1]);
    float m = fmaxf(v0, v1);
    float lse = m + logf(expf(v0 - m) + expf(v1 - m));
    out[i * 2 + 0] = v0 - lse;
    out[i * 2 + 1] = v1 - lse;

    cursor_buf[i] = 0;  // restore invariant for next call
}

// ---------------- launch ----------------

extern "C" void kernel_launch(void* const* d_in, const int* in_sizes, int n_in,
                              void* d_out, int out_size) {
    const float* x  = (const float*)d_in[0];
    const int*   ei = (const int*)d_in[1];
    const float* W1 = (const float*)d_in[2];
    const float* b1 = (const float*)d_in[3];
    const float* W2 = (const float*)d_in[4];
    const float* b2 = (const float*)d_in[5];
    const float* W3 = (const float*)d_in[6];
    const float* b3 = (const float*)d_in[7];
    const float* W4 = (const float*)d_in[8];
    const float* b4 = (const float*)d_in[9];
    float* out = (float*)d_out;

    const int T = 256;
    const int nodeB = (N_NODES + T - 1) / T;
    const int quadEdgeB = (N_EDGES / 4 + T - 1) / T;

    // CSR build (fixed-stride segments; cursors pre-zeroed invariant)
    fill_kernel<<<quadEdgeB, T>>>(ei);
    pad_kernel<<<nodeB, T>>>(x);

    // Layer 1 agg (8-lane groups, 5 active), then fused GEMM1+relu+GEMM2
    agg_pre_kernel<<<(N_NODES * 8 + T - 1) / T, T>>>();
    gemm12_kernel<<<nodeB, T>>>(W1, b1, W2);

    // Layer 2 agg + fused GEMM3 (8-lane groups)
    agg32_g3_kernel<<<(N_NODES * 8 + T - 1) / T, T>>>(b2, W3);

    // Layer 3 agg + fused GEMM4 (4-lane groups)
    agg16_g4_kernel<<<(N_NODES * 4 + T - 1) / T, T>>>(b3, W4);

    // Layer 4 agg + log_softmax (+ cursor reset)
    agg2_logsoftmax_kernel<<<nodeB, T>>>(b4, out);
}